// round 1
// baseline (speedup 1.0000x reference)
#include <cuda_runtime.h>
#include <math.h>

#define D_MODEL   1536
#define NUM_HEADS 16
#define QGROUPS   4
#define HEAD_DIM  96
#define QKV_OUT   2304      // 16*96 + 2*4*96
#define B_SZ      2
#define N_TOK     2048
#define BN_TOK    (B_SZ * N_TOK)

// ---------------- scratch (no allocations allowed) ----------------
__device__ float g_qkv [(size_t)BN_TOK * QKV_OUT];   // ~37.7 MB
__device__ float g_attn[(size_t)BN_TOK * D_MODEL];   // ~25.2 MB

// =====================================================================
// SGEMM (NT): C[M,N] = A[M,K] * B[N,K]^T , all K-major row storage.
// 128x128 block tile, BK=16, 256 threads, 8x8 micro-tile.
// =====================================================================
#define BK 16
__global__ __launch_bounds__(256) void sgemm_nt(const float* __restrict__ A,
                                                const float* __restrict__ B,
                                                float* __restrict__ C,
                                                int M, int N, int K) {
    __shared__ float As[BK][132];   // stride 132 floats: 16B-aligned rows
    __shared__ float Bs[BK][132];

    const int tid = threadIdx.x;
    const int tx  = tid & 15;        // 0..15 -> C col group
    const int ty  = tid >> 4;        // 0..15 -> C row group
    const int bm  = blockIdx.y * 128;
    const int bn  = blockIdx.x * 128;

    float acc[8][8];
#pragma unroll
    for (int i = 0; i < 8; i++)
#pragma unroll
        for (int j = 0; j < 8; j++) acc[i][j] = 0.f;

    const float* Ab = A + (size_t)bm * K;
    const float* Bb = B + (size_t)bn * K;

    const int lrow = tid >> 2;       // 0..63
    const int lk4  = tid & 3;        // float4 index within BK=16

    for (int kt = 0; kt < K; kt += BK) {
#pragma unroll
        for (int half = 0; half < 2; half++) {
            int row = lrow + half * 64;
            float4 va = *(const float4*)(Ab + (size_t)row * K + kt + lk4 * 4);
            As[lk4*4+0][row] = va.x; As[lk4*4+1][row] = va.y;
            As[lk4*4+2][row] = va.z; As[lk4*4+3][row] = va.w;
            float4 vb = *(const float4*)(Bb + (size_t)row * K + kt + lk4 * 4);
            Bs[lk4*4+0][row] = vb.x; Bs[lk4*4+1][row] = vb.y;
            Bs[lk4*4+2][row] = vb.z; Bs[lk4*4+3][row] = vb.w;
        }
        __syncthreads();

#pragma unroll
        for (int kk = 0; kk < BK; kk++) {
            float a[8], b[8];
            *(float4*)&a[0] = *(float4*)&As[kk][ty * 8];
            *(float4*)&a[4] = *(float4*)&As[kk][ty * 8 + 4];
            *(float4*)&b[0] = *(float4*)&Bs[kk][tx * 8];
            *(float4*)&b[4] = *(float4*)&Bs[kk][tx * 8 + 4];
#pragma unroll
            for (int i = 0; i < 8; i++)
#pragma unroll
                for (int j = 0; j < 8; j++) acc[i][j] += a[i] * b[j];
        }
        __syncthreads();
    }

#pragma unroll
    for (int i = 0; i < 8; i++) {
        float* Crow = C + (size_t)(bm + ty * 8 + i) * N + bn + tx * 8;
        *(float4*)(Crow)     = make_float4(acc[i][0], acc[i][1], acc[i][2], acc[i][3]);
        *(float4*)(Crow + 4) = make_float4(acc[i][4], acc[i][5], acc[i][6], acc[i][7]);
    }
}

// =====================================================================
// RoPE-3D applied in place to Q (16 heads) and K (4 groups) of g_qkv.
// Grid dims are read from device scalars.
// =====================================================================
__global__ void rope_kernel(const int* __restrict__ pgt,
                            const int* __restrict__ pgh,
                            const int* __restrict__ pgw) {
    const int token = blockIdx.x;                 // 0..BN_TOK-1
    const int GH = *pgh, GW = *pgw;
    const int n = token % N_TOK;
    int posv[3];
    posv[0] = n / (GH * GW);
    posv[1] = (n / GW) % GH;
    posv[2] = n % GW;

    const size_t base = (size_t)token * QKV_OUT;
    for (int idx = threadIdx.x; idx < 20 * 48; idx += blockDim.x) {
        const int head = idx / 48;                // 0..15 = Q heads, 16..19 = K groups
        const int pi   = idx % 48;
        const int axis = pi >> 4;                 // 0..2
        const int p    = pi & 15;                 // 0..15 pairs
        float freq = powf(10000.0f, -(float)p / 16.0f);
        float ang  = (float)posv[axis] * freq;
        float s, c;
        sincosf(ang, &s, &c);
        int off = (head < 16) ? (head * HEAD_DIM + axis * 32 + 2 * p)
                              : (1536 + (head - 16) * HEAD_DIM + axis * 32 + 2 * p);
        float x0 = g_qkv[base + off];
        float x1 = g_qkv[base + off + 1];
        g_qkv[base + off]     = x0 * c - x1 * s;
        g_qkv[base + off + 1] = x0 * s + x1 * c;
    }
}

// =====================================================================
// Flash attention: per (b, head, 64-query tile). 64x64 KV tiles.
// 256 threads as 16x16; interleaved row/col ownership for conflict-free LDS.
//   S micro-tile: 4 q-rows (ty+16r) x 4 k-cols (tx+16c)
//   O micro-tile: 4 q-rows x 6 out-cols (tx+16c)
// =====================================================================
#define QS_STRIDE 97
#define PS_STRIDE 65
#define ATT_SMEM_FLOATS (64*QS_STRIDE + 64*QS_STRIDE + 64*HEAD_DIM + 64*PS_STRIDE)
#define ATT_SMEM_BYTES  (ATT_SMEM_FLOATS * 4)

__global__ __launch_bounds__(256) void attn_kernel() {
    extern __shared__ float sm[];
    float* Qs = sm;                         // [64][97]
    float* Ks = Qs + 64 * QS_STRIDE;        // [64][97]
    float* Vs = Ks + 64 * QS_STRIDE;        // [64][96]
    float* Ps = Vs + 64 * HEAD_DIM;         // [64][65]

    const int tid = threadIdx.x;
    const int tx  = tid & 15;
    const int ty  = tid >> 4;
    const int qtile = blockIdx.x;           // 0..31
    const int hh    = blockIdx.y;           // 0..15
    const int b     = blockIdx.z;           // 0..1
    const int g     = hh >> 2;              // KV group (repeat_interleave)

    const float scale = rsqrtf((float)HEAD_DIM);

    // ---- load Q tile ----
    {
        const size_t qbase = ((size_t)(b * N_TOK) + qtile * 64) * QKV_OUT + hh * HEAD_DIM;
        for (int i = tid; i < 64 * 24; i += 256) {
            int r = i / 24, c4 = i % 24;
            float4 v = *(const float4*)(g_qkv + qbase + (size_t)r * QKV_OUT + c4 * 4);
            float* q = &Qs[r * QS_STRIDE + c4 * 4];
            q[0] = v.x; q[1] = v.y; q[2] = v.z; q[3] = v.w;
        }
    }

    float m_i[4], l_i[4], acc[4][6];
#pragma unroll
    for (int r = 0; r < 4; r++) {
        m_i[r] = -INFINITY; l_i[r] = 0.f;
#pragma unroll
        for (int c = 0; c < 6; c++) acc[r][c] = 0.f;
    }

    for (int jt = 0; jt < N_TOK / 64; jt++) {
        // ---- load K,V tiles ----
        const size_t kvtok = (size_t)(b * N_TOK) + jt * 64;
        const int koff = 1536 + g * HEAD_DIM;
        const int voff = 1920 + g * HEAD_DIM;
        __syncthreads();   // protect Ks/Vs/Ps from previous iteration readers
        for (int i = tid; i < 64 * 24; i += 256) {
            int r = i / 24, c4 = i % 24;
            const float* rowp = g_qkv + (kvtok + r) * QKV_OUT;
            float4 kv = *(const float4*)(rowp + koff + c4 * 4);
            float* ks = &Ks[r * QS_STRIDE + c4 * 4];
            ks[0] = kv.x; ks[1] = kv.y; ks[2] = kv.z; ks[3] = kv.w;
            float4 vv = *(const float4*)(rowp + voff + c4 * 4);
            *(float4*)&Vs[r * HEAD_DIM + c4 * 4] = vv;
        }
        __syncthreads();

        // ---- S = Q K^T * scale ----
        float s[4][4];
#pragma unroll
        for (int r = 0; r < 4; r++)
#pragma unroll
            for (int c = 0; c < 4; c++) s[r][c] = 0.f;

#pragma unroll 4
        for (int k = 0; k < HEAD_DIM; k++) {
            float qv[4], kv[4];
#pragma unroll
            for (int r = 0; r < 4; r++) qv[r] = Qs[(ty + 16 * r) * QS_STRIDE + k];
#pragma unroll
            for (int c = 0; c < 4; c++) kv[c] = Ks[(tx + 16 * c) * QS_STRIDE + k];
#pragma unroll
            for (int r = 0; r < 4; r++)
#pragma unroll
                for (int c = 0; c < 4; c++) s[r][c] += qv[r] * kv[c];
        }

        // ---- online softmax update ----
#pragma unroll
        for (int r = 0; r < 4; r++) {
            float mx = -INFINITY;
#pragma unroll
            for (int c = 0; c < 4; c++) {
                s[r][c] *= scale;
                mx = fmaxf(mx, s[r][c]);
            }
#pragma unroll
            for (int o = 8; o >= 1; o >>= 1)
                mx = fmaxf(mx, __shfl_xor_sync(0xffffffffu, mx, o, 16));
            float mnew  = fmaxf(m_i[r], mx);
            float alpha = __expf(m_i[r] - mnew);
            m_i[r] = mnew;
            float rs = 0.f;
#pragma unroll
            for (int c = 0; c < 4; c++) {
                s[r][c] = __expf(s[r][c] - mnew);
                rs += s[r][c];
            }
#pragma unroll
            for (int o = 8; o >= 1; o >>= 1)
                rs += __shfl_xor_sync(0xffffffffu, rs, o, 16);
            l_i[r] = l_i[r] * alpha + rs;
#pragma unroll
            for (int c = 0; c < 6; c++) acc[r][c] *= alpha;
        }

        // ---- write P, then O += P V ----
#pragma unroll
        for (int r = 0; r < 4; r++)
#pragma unroll
            for (int c = 0; c < 4; c++)
                Ps[(ty + 16 * r) * PS_STRIDE + (tx + 16 * c)] = s[r][c];
        __syncthreads();

#pragma unroll 4
        for (int mI = 0; mI < 64; mI++) {
            float pv[4], vv[6];
#pragma unroll
            for (int r = 0; r < 4; r++) pv[r] = Ps[(ty + 16 * r) * PS_STRIDE + mI];
#pragma unroll
            for (int c = 0; c < 6; c++) vv[c] = Vs[mI * HEAD_DIM + tx + 16 * c];
#pragma unroll
            for (int r = 0; r < 4; r++)
#pragma unroll
                for (int c = 0; c < 6; c++) acc[r][c] += pv[r] * vv[c];
        }
    }

    // ---- epilogue: normalize, scatter to [b,n,h,d] ----
#pragma unroll
    for (int r = 0; r < 4; r++) {
        float inv = 1.f / l_i[r];
        size_t row = (size_t)(b * N_TOK) + qtile * 64 + ty + 16 * r;
        float* op = g_attn + row * D_MODEL + hh * HEAD_DIM;
#pragma unroll
        for (int c = 0; c < 6; c++) op[tx + 16 * c] = acc[r][c] * inv;
    }
}

// =====================================================================
extern "C" void kernel_launch(void* const* d_in, const int* in_sizes, int n_in,
                              void* d_out, int out_size) {
    const float* x     = (const float*)d_in[0];
    const float* w_qkv = (const float*)d_in[1];
    const float* w_o   = (const float*)d_in[2];
    const int*   gt    = (const int*)d_in[3];
    const int*   gh    = (const int*)d_in[4];
    const int*   gw    = (const int*)d_in[5];
    float* out = (float*)d_out;
    (void)in_sizes; (void)n_in; (void)out_size; (void)gt;

    float *qkv_ptr, *attn_ptr;
    cudaGetSymbolAddress((void**)&qkv_ptr,  g_qkv);
    cudaGetSymbolAddress((void**)&attn_ptr, g_attn);

    cudaFuncSetAttribute(attn_kernel, cudaFuncAttributeMaxDynamicSharedMemorySize,
                         ATT_SMEM_BYTES);

    // 1) QKV projection: [4096,1536] @ [2304,1536]^T
    sgemm_nt<<<dim3(QKV_OUT / 128, BN_TOK / 128), 256>>>(
        x, w_qkv, qkv_ptr, BN_TOK, QKV_OUT, D_MODEL);

    // 2) RoPE-3D in place on Q and K
    rope_kernel<<<BN_TOK, 128>>>(gt, gh, gw);

    // 3) GQA flash attention -> g_attn [4096,1536]
    attn_kernel<<<dim3(N_TOK / 64, NUM_HEADS, B_SZ), 256, ATT_SMEM_BYTES>>>();

    // 4) Output projection: [4096,1536] @ [1536,1536]^T -> d_out
    sgemm_nt<<<dim3(D_MODEL / 128, BN_TOK / 128), 256>>>(
        attn_ptr, w_o, out, BN_TOK, D_MODEL, D_MODEL);
}

// round 7
// speedup vs baseline: 1.0167x; 1.0167x over previous
#include <cuda_runtime.h>
#include <math.h>
#include <stdint.h>

#define D_MODEL   1536
#define NUM_HEADS 16
#define QGROUPS   4
#define HEAD_DIM  96
#define QKV_OUT   2304      // 16*96 + 2*4*96
#define B_SZ      2
#define N_TOK     2048
#define BN_TOK    (B_SZ * N_TOK)

// ---------------- scratch (no allocations allowed) ----------------
__device__ float g_qkv [(size_t)BN_TOK * QKV_OUT];   // ~37.7 MB
__device__ float g_attn[(size_t)BN_TOK * D_MODEL];   // ~25.2 MB

__device__ __forceinline__ float tf32r(float x) {
    uint32_t u;
    asm("cvt.rna.tf32.f32 %0, %1;" : "=r"(u) : "f"(x));
    return __uint_as_float(u);
}
__device__ __forceinline__ void mma_tf32(float* c, const uint32_t* a, const uint32_t* b) {
    asm volatile(
        "mma.sync.aligned.m16n8k8.row.col.f32.tf32.tf32.f32 "
        "{%0,%1,%2,%3}, {%4,%5,%6,%7}, {%8,%9}, {%0,%1,%2,%3};"
        : "+f"(c[0]), "+f"(c[1]), "+f"(c[2]), "+f"(c[3])
        : "r"(a[0]), "r"(a[1]), "r"(a[2]), "r"(a[3]), "r"(b[0]), "r"(b[1]));
}

// =====================================================================
// mma.sync tf32 GEMM (NT): C[M,N] = A[M,K] * B[N,K]^T, K-major rows.
// Block 128x128, BK=16, 256 threads = 8 warps (2M x 4N), warp = 64x32.
// 3-term tf32 hi/lo split (hh + h*l + l*h) for fp32-grade accuracy.
// SMEM holds pre-packed MMA fragments: all LDS are conflict-free lds.64.
//   frag layout [half(k8)][rowgroup(8 rows)][lane] -> float2 (k0+q, k0+q+4)
// =====================================================================
#define BM 128
#define BN 128
#define BKK 16
// float2 [2][16][32] = 8 KB each
__global__ __launch_bounds__(256, 2) void gemm_mma(const float* __restrict__ A,
                                                   const float* __restrict__ B,
                                                   float* __restrict__ C,
                                                   int M, int N, int K) {
    __shared__ float2 Ah[2][16][32];
    __shared__ float2 Al[2][16][32];
    __shared__ float2 Bh[2][16][32];
    __shared__ float2 Bl[2][16][32];

    const int tid   = threadIdx.x;
    const int lane  = tid & 31;
    const int w     = tid >> 5;
    const int warpM = w >> 2;          // 0..1
    const int warpN = w & 3;           // 0..3
    const int bm    = blockIdx.y * BM;
    const int bn    = blockIdx.x * BN;

    float acc[4][4][4];
#pragma unroll
    for (int t = 0; t < 4; t++)
#pragma unroll
        for (int u = 0; u < 4; u++)
#pragma unroll
            for (int q = 0; q < 4; q++) acc[t][u][q] = 0.f;

    const float* Ab = A + (size_t)bm * K;
    const float* Bb = B + (size_t)bn * K;

    for (int kt = 0; kt < K; kt += BKK) {
        // ---- stage gmem -> regs (before overwriting smem) ----
        float4 av[2], bv[2];
#pragma unroll
        for (int j = 0; j < 2; j++) {
            int idx = tid + 256 * j;          // 0..511
            int r = idx >> 2, c4 = idx & 3;   // r: tile row, c4: float4 within BK
            av[j] = *(const float4*)(Ab + (size_t)r * K + kt + c4 * 4);
            bv[j] = *(const float4*)(Bb + (size_t)r * K + kt + c4 * 4);
        }
        __syncthreads();   // all warps done reading previous fragments

        // ---- split to tf32 hi/lo, store as fragments ----
#pragma unroll
        for (int j = 0; j < 2; j++) {
            int idx = tid + 256 * j;
            int r = idx >> 2, c4 = idx & 3;
            int h    = c4 >> 1;               // k8 half
            int comp = c4 & 1;                // float2 component (k0+q vs k0+q+4)
            int rg   = r >> 3;
            int lb   = (r & 7) * 4;           // lane base = g*4
            float va[4] = {av[j].x, av[j].y, av[j].z, av[j].w};
            float vb[4] = {bv[j].x, bv[j].y, bv[j].z, bv[j].w};
#pragma unroll
            for (int q = 0; q < 4; q++) {
                float ahv = tf32r(va[q]);
                float alv = tf32r(va[q] - ahv);
                float bhv = tf32r(vb[q]);
                float blv = tf32r(vb[q] - bhv);
                ((float*)&Ah[h][rg][lb + q])[comp] = ahv;
                ((float*)&Al[h][rg][lb + q])[comp] = alv;
                ((float*)&Bh[h][rg][lb + q])[comp] = bhv;
                ((float*)&Bl[h][rg][lb + q])[comp] = blv;
            }
        }
        __syncthreads();

        // ---- compute: 2 k8 halves x (hh + hl + lh) x 16 mma ----
#pragma unroll
        for (int h = 0; h < 2; h++) {
            uint32_t ah[4][4], al[4][4];      // [t][a0..a3]
            uint32_t bh[4][2], bl[4][2];      // [u][b0..b1]
#pragma unroll
            for (int t = 0; t < 4; t++) {
                int g0 = (warpM * 4 + t) * 2;
                float2 p0 = Ah[h][g0][lane];
                float2 p1 = Ah[h][g0 + 1][lane];
                ah[t][0] = __float_as_uint(p0.x); ah[t][1] = __float_as_uint(p1.x);
                ah[t][2] = __float_as_uint(p0.y); ah[t][3] = __float_as_uint(p1.y);
                float2 q0 = Al[h][g0][lane];
                float2 q1 = Al[h][g0 + 1][lane];
                al[t][0] = __float_as_uint(q0.x); al[t][1] = __float_as_uint(q1.x);
                al[t][2] = __float_as_uint(q0.y); al[t][3] = __float_as_uint(q1.y);
            }
#pragma unroll
            for (int u = 0; u < 4; u++) {
                float2 p = Bh[h][warpN * 4 + u][lane];
                bh[u][0] = __float_as_uint(p.x); bh[u][1] = __float_as_uint(p.y);
                float2 q = Bl[h][warpN * 4 + u][lane];
                bl[u][0] = __float_as_uint(q.x); bl[u][1] = __float_as_uint(q.y);
            }
#pragma unroll
            for (int t = 0; t < 4; t++)
#pragma unroll
                for (int u = 0; u < 4; u++) {
                    mma_tf32(acc[t][u], ah[t], bh[u]);   // hi*hi
                    mma_tf32(acc[t][u], ah[t], bl[u]);   // hi*lo
                    mma_tf32(acc[t][u], al[t], bh[u]);   // lo*hi
                }
        }
    }

    // ---- epilogue: c0,c1 = (row g, cols 2q,2q+1); c2,c3 = row g+8 ----
    const int g = lane >> 2, q2 = (lane & 3) * 2;
#pragma unroll
    for (int t = 0; t < 4; t++) {
        int m0 = bm + warpM * 64 + t * 16 + g;
#pragma unroll
        for (int u = 0; u < 4; u++) {
            int n0 = bn + warpN * 32 + u * 8 + q2;
            *(float2*)(C + (size_t)m0 * N + n0)       = make_float2(acc[t][u][0], acc[t][u][1]);
            *(float2*)(C + (size_t)(m0 + 8) * N + n0) = make_float2(acc[t][u][2], acc[t][u][3]);
        }
    }
}

// =====================================================================
// RoPE-3D applied in place to Q (16 heads) and K (4 groups) of g_qkv.
// =====================================================================
__global__ void rope_kernel(const int* __restrict__ pgt,
                            const int* __restrict__ pgh,
                            const int* __restrict__ pgw) {
    const int token = blockIdx.x;
    const int GH = *pgh, GW = *pgw;
    const int n = token % N_TOK;
    int posv[3];
    posv[0] = n / (GH * GW);
    posv[1] = (n / GW) % GH;
    posv[2] = n % GW;

    const size_t base = (size_t)token * QKV_OUT;
    for (int idx = threadIdx.x; idx < 20 * 48; idx += blockDim.x) {
        const int head = idx / 48;
        const int pi   = idx % 48;
        const int axis = pi >> 4;
        const int p    = pi & 15;
        float freq = powf(10000.0f, -(float)p / 16.0f);
        float ang  = (float)posv[axis] * freq;
        float s, c;
        sincosf(ang, &s, &c);
        int off = (head < 16) ? (head * HEAD_DIM + axis * 32 + 2 * p)
                              : (1536 + (head - 16) * HEAD_DIM + axis * 32 + 2 * p);
        float x0 = g_qkv[base + off];
        float x1 = g_qkv[base + off + 1];
        g_qkv[base + off]     = x0 * c - x1 * s;
        g_qkv[base + off + 1] = x0 * s + x1 * c;
    }
}

// =====================================================================
// Flash attention (fp32 FFMA, unchanged this round)
// =====================================================================
#define QS_STRIDE 97
#define PS_STRIDE 65
#define ATT_SMEM_FLOATS (64*QS_STRIDE + 64*QS_STRIDE + 64*HEAD_DIM + 64*PS_STRIDE)
#define ATT_SMEM_BYTES  (ATT_SMEM_FLOATS * 4)

__global__ __launch_bounds__(256) void attn_kernel() {
    extern __shared__ float smf[];
    float* Qs = smf;
    float* Ks = Qs + 64 * QS_STRIDE;
    float* Vs = Ks + 64 * QS_STRIDE;
    float* Ps = Vs + 64 * HEAD_DIM;

    const int tid = threadIdx.x;
    const int tx  = tid & 15;
    const int ty  = tid >> 4;
    const int qtile = blockIdx.x;
    const int hh    = blockIdx.y;
    const int b     = blockIdx.z;
    const int g     = hh >> 2;

    const float scale = rsqrtf((float)HEAD_DIM);

    {
        const size_t qbase = ((size_t)(b * N_TOK) + qtile * 64) * QKV_OUT + hh * HEAD_DIM;
        for (int i = tid; i < 64 * 24; i += 256) {
            int r = i / 24, c4 = i % 24;
            float4 v = *(const float4*)(g_qkv + qbase + (size_t)r * QKV_OUT + c4 * 4);
            float* q = &Qs[r * QS_STRIDE + c4 * 4];
            q[0] = v.x; q[1] = v.y; q[2] = v.z; q[3] = v.w;
        }
    }

    float m_i[4], l_i[4], acc[4][6];
#pragma unroll
    for (int r = 0; r < 4; r++) {
        m_i[r] = -INFINITY; l_i[r] = 0.f;
#pragma unroll
        for (int c = 0; c < 6; c++) acc[r][c] = 0.f;
    }

    for (int jt = 0; jt < N_TOK / 64; jt++) {
        const size_t kvtok = (size_t)(b * N_TOK) + jt * 64;
        const int koff = 1536 + g * HEAD_DIM;
        const int voff = 1920 + g * HEAD_DIM;
        __syncthreads();
        for (int i = tid; i < 64 * 24; i += 256) {
            int r = i / 24, c4 = i % 24;
            const float* rowp = g_qkv + (kvtok + r) * QKV_OUT;
            float4 kv = *(const float4*)(rowp + koff + c4 * 4);
            float* ks = &Ks[r * QS_STRIDE + c4 * 4];
            ks[0] = kv.x; ks[1] = kv.y; ks[2] = kv.z; ks[3] = kv.w;
            float4 vv = *(const float4*)(rowp + voff + c4 * 4);
            *(float4*)&Vs[r * HEAD_DIM + c4 * 4] = vv;
        }
        __syncthreads();

        float s[4][4];
#pragma unroll
        for (int r = 0; r < 4; r++)
#pragma unroll
            for (int c = 0; c < 4; c++) s[r][c] = 0.f;

#pragma unroll 4
        for (int k = 0; k < HEAD_DIM; k++) {
            float qv[4], kv[4];
#pragma unroll
            for (int r = 0; r < 4; r++) qv[r] = Qs[(ty + 16 * r) * QS_STRIDE + k];
#pragma unroll
            for (int c = 0; c < 4; c++) kv[c] = Ks[(tx + 16 * c) * QS_STRIDE + k];
#pragma unroll
            for (int r = 0; r < 4; r++)
#pragma unroll
                for (int c = 0; c < 4; c++) s[r][c] += qv[r] * kv[c];
        }

#pragma unroll
        for (int r = 0; r < 4; r++) {
            float mx = -INFINITY;
#pragma unroll
            for (int c = 0; c < 4; c++) {
                s[r][c] *= scale;
                mx = fmaxf(mx, s[r][c]);
            }
#pragma unroll
            for (int o = 8; o >= 1; o >>= 1)
                mx = fmaxf(mx, __shfl_xor_sync(0xffffffffu, mx, o, 16));
            float mnew  = fmaxf(m_i[r], mx);
            float alpha = __expf(m_i[r] - mnew);
            m_i[r] = mnew;
            float rs = 0.f;
#pragma unroll
            for (int c = 0; c < 4; c++) {
                s[r][c] = __expf(s[r][c] - mnew);
                rs += s[r][c];
            }
#pragma unroll
            for (int o = 8; o >= 1; o >>= 1)
                rs += __shfl_xor_sync(0xffffffffu, rs, o, 16);
            l_i[r] = l_i[r] * alpha + rs;
#pragma unroll
            for (int c = 0; c < 6; c++) acc[r][c] *= alpha;
        }

#pragma unroll
        for (int r = 0; r < 4; r++)
#pragma unroll
            for (int c = 0; c < 4; c++)
                Ps[(ty + 16 * r) * PS_STRIDE + (tx + 16 * c)] = s[r][c];
        __syncthreads();

#pragma unroll 4
        for (int mI = 0; mI < 64; mI++) {
            float pv[4], vv[6];
#pragma unroll
            for (int r = 0; r < 4; r++) pv[r] = Ps[(ty + 16 * r) * PS_STRIDE + mI];
#pragma unroll
            for (int c = 0; c < 6; c++) vv[c] = Vs[mI * HEAD_DIM + tx + 16 * c];
#pragma unroll
            for (int r = 0; r < 4; r++)
#pragma unroll
                for (int c = 0; c < 6; c++) acc[r][c] += pv[r] * vv[c];
        }
    }

#pragma unroll
    for (int r = 0; r < 4; r++) {
        float inv = 1.f / l_i[r];
        size_t row = (size_t)(b * N_TOK) + qtile * 64 + ty + 16 * r;
        float* op = g_attn + row * D_MODEL + hh * HEAD_DIM;
#pragma unroll
        for (int c = 0; c < 6; c++) op[tx + 16 * c] = acc[r][c] * inv;
    }
}

// =====================================================================
extern "C" void kernel_launch(void* const* d_in, const int* in_sizes, int n_in,
                              void* d_out, int out_size) {
    const float* x     = (const float*)d_in[0];
    const float* w_qkv = (const float*)d_in[1];
    const float* w_o   = (const float*)d_in[2];
    const int*   gt    = (const int*)d_in[3];
    const int*   gh    = (const int*)d_in[4];
    const int*   gw    = (const int*)d_in[5];
    float* out = (float*)d_out;
    (void)in_sizes; (void)n_in; (void)out_size; (void)gt;

    float *qkv_ptr, *attn_ptr;
    cudaGetSymbolAddress((void**)&qkv_ptr,  g_qkv);
    cudaGetSymbolAddress((void**)&attn_ptr, g_attn);

    cudaFuncSetAttribute(attn_kernel, cudaFuncAttributeMaxDynamicSharedMemorySize,
                         ATT_SMEM_BYTES);

    // 1) QKV projection: [4096,1536] @ [2304,1536]^T  (mma.sync tf32 3-term)
    gemm_mma<<<dim3(QKV_OUT / BN, BN_TOK / BM), 256>>>(
        x, w_qkv, qkv_ptr, BN_TOK, QKV_OUT, D_MODEL);

    // 2) RoPE-3D in place on Q and K
    rope_kernel<<<BN_TOK, 128>>>(gt, gh, gw);

    // 3) GQA flash attention -> g_attn [4096,1536]
    attn_kernel<<<dim3(N_TOK / 64, NUM_HEADS, B_SZ), 256, ATT_SMEM_BYTES>>>();

    // 4) Output projection: [4096,1536] @ [1536,1536]^T -> d_out (mma.sync tf32)
    gemm_mma<<<dim3(D_MODEL / BN, BN_TOK / BM), 256>>>(
        attn_ptr, w_o, out, BN_TOK, D_MODEL, D_MODEL);
}